// round 3
// baseline (speedup 1.0000x reference)
#include <cuda_runtime.h>

#define TPB 256
#define NBLK 2048
#define VPT 4

// Per-block partials (device globals — no allocation allowed). Fully
// overwritten each call by the reduce kernel -> deterministic.
__device__ double g_part[4][NBLK];   // [0]=class [1]=bbox [2]=sigma [3]=neg
__device__ int    g_npos[NBLK];
__device__ int    g_last[NBLK];

__inline__ __device__ double warp_sum_d(double v) {
    #pragma unroll
    for (int o = 16; o > 0; o >>= 1) v += __shfl_down_sync(0xffffffffu, v, o);
    return v;
}
__inline__ __device__ int warp_sum_i(int v) {
    #pragma unroll
    for (int o = 16; o > 0; o >>= 1) v += __shfl_down_sync(0xffffffffu, v, o);
    return v;
}
__inline__ __device__ int warp_max_i(int v) {
    #pragma unroll
    for (int o = 16; o > 0; o >>= 1) v = max(v, __shfl_down_sync(0xffffffffu, v, o));
    return v;
}

__global__ __launch_bounds__(TPB, 2)
void rpn_reduce_kernel(const float4* __restrict__ bbox,   // [4M]
                       const float2* __restrict__ logits, // [4M]
                       const float4* __restrict__ sigma,  // [4M]
                       const float4* __restrict__ gt,     // [4M]
                       const int* __restrict__ label,     // [4M]
                       const int* __restrict__ vidx,      // [V]
                       int V) {
    const float EPS = 1e-10f;
    double acc_c = 0.0, acc_b = 0.0, acc_s = 0.0, acc_n = 0.0;
    int npos = 0, lastp = -1;

    int base   = (blockIdx.x * TPB + threadIdx.x) * VPT;
    int stride = gridDim.x * TPB * VPT;

    for (int i0 = base; i0 < V; i0 += stride) {
        int idx[VPT];
        int n = V - i0;
        if (n >= VPT) {
            int4 a4 = *reinterpret_cast<const int4*>(vidx + i0);
            idx[0] = a4.x; idx[1] = a4.y; idx[2] = a4.z; idx[3] = a4.w;
            n = VPT;
        } else {
            #pragma unroll
            for (int j = 0; j < VPT; j++) idx[j] = vidx[i0 + (j < n ? j : 0)];
        }

        // Front-batch all gathers: 20 independent loads in flight.
        int lbl[VPT]; float2 lg[VPT]; float4 p[VPT], t[VPT], s[VPT];
        #pragma unroll
        for (int j = 0; j < VPT; j++) {
            int a = idx[j];
            lbl[j] = label[a];
            lg[j]  = logits[a];
            p[j]   = bbox[a];
            t[j]   = gt[a];
            s[j]   = sigma[a];
        }

        #pragma unroll
        for (int j = 0; j < VPT; j++) {
            bool live = (j < n);
            bool pos  = (lbl[j] == 1);

            // -log_softmax at label (stable 2-class LSE)
            float m   = fmaxf(lg[j].x, lg[j].y);
            float d   = -fabsf(lg[j].x - lg[j].y);
            float lse = m + __logf(1.0f + __expf(d));
            float sel = pos ? lg[j].y : lg[j].x;
            float cls = lse - sel;

            float dx = p[j].x - t[j].x, dy = p[j].y - t[j].y,
                  dz = p[j].z - t[j].z, dw = p[j].w - t[j].w;
            float e0 = EPS + s[j].x, e1 = EPS + s[j].y,
                  e2 = EPS + s[j].z, e3 = EPS + s[j].w;
            float r0 = __fdividef(1.0f, e0), r1 = __fdividef(1.0f, e1),
                  r2 = __fdividef(1.0f, e2), r3 = __fdividef(1.0f, e3);

            float bsum = 0.5f * (dx * dx * r0 + dy * dy * r1 +
                                 dz * dz * r2 + dw * dw * r3);
            float lsum = 0.5f * (__logf(e0 * e1) + __logf(e2 * e3));
            float nsum = r0 + r1 + r2 + r3;

            if (live) {
                acc_c += (double)cls;
                if (pos) {
                    acc_b += (double)bsum;
                    acc_s += (double)lsum;
                    npos++;
                    lastp = i0 + j;
                } else {
                    acc_n += (double)nsum;
                }
            }
        }
    }

    // Block reduction -> per-block partials
    __shared__ double sh[4][TPB / 32];
    __shared__ int    shi[2][TPB / 32];
    int lane = threadIdx.x & 31;
    int wid  = threadIdx.x >> 5;

    acc_c = warp_sum_d(acc_c);
    acc_b = warp_sum_d(acc_b);
    acc_s = warp_sum_d(acc_s);
    acc_n = warp_sum_d(acc_n);
    npos  = warp_sum_i(npos);
    lastp = warp_max_i(lastp);
    if (lane == 0) {
        sh[0][wid] = acc_c; sh[1][wid] = acc_b;
        sh[2][wid] = acc_s; sh[3][wid] = acc_n;
        shi[0][wid] = npos; shi[1][wid] = lastp;
    }
    __syncthreads();
    if (wid == 0) {
        const int NW = TPB / 32;
        double c  = (lane < NW) ? sh[0][lane] : 0.0;
        double b  = (lane < NW) ? sh[1][lane] : 0.0;
        double s2 = (lane < NW) ? sh[2][lane] : 0.0;
        double n2 = (lane < NW) ? sh[3][lane] : 0.0;
        int np = (lane < NW) ? shi[0][lane] : 0;
        int lp = (lane < NW) ? shi[1][lane] : -1;
        c = warp_sum_d(c); b = warp_sum_d(b);
        s2 = warp_sum_d(s2); n2 = warp_sum_d(n2);
        np = warp_sum_i(np); lp = warp_max_i(lp);
        if (lane == 0) {
            g_part[0][blockIdx.x] = c;
            g_part[1][blockIdx.x] = b;
            g_part[2][blockIdx.x] = s2;
            g_part[3][blockIdx.x] = n2;
            g_npos[blockIdx.x]    = np;
            g_last[blockIdx.x]    = lp;
        }
    }
}

__global__ __launch_bounds__(TPB)
void rpn_finalize_kernel(const float4* __restrict__ bbox,
                         const float4* __restrict__ gt,
                         const int* __restrict__ vidx,
                         float* __restrict__ out, int V, int nblk) {
    __shared__ double sh[4][TPB / 32];
    __shared__ int    shi[2][TPB / 32];
    double c = 0.0, b = 0.0, s2 = 0.0, n2 = 0.0;
    int np = 0, lp = -1;
    for (int i = threadIdx.x; i < nblk; i += TPB) {
        c  += g_part[0][i];
        b  += g_part[1][i];
        s2 += g_part[2][i];
        n2 += g_part[3][i];
        np += g_npos[i];
        lp  = max(lp, g_last[i]);
    }
    int lane = threadIdx.x & 31;
    int wid  = threadIdx.x >> 5;
    c = warp_sum_d(c); b = warp_sum_d(b);
    s2 = warp_sum_d(s2); n2 = warp_sum_d(n2);
    np = warp_sum_i(np); lp = warp_max_i(lp);
    if (lane == 0) {
        sh[0][wid] = c; sh[1][wid] = b; sh[2][wid] = s2; sh[3][wid] = n2;
        shi[0][wid] = np; shi[1][wid] = lp;
    }
    __syncthreads();
    if (threadIdx.x == 0) {
        const int NW = TPB / 32;
        double fc = 0, fb = 0, fs = 0, fn = 0;
        int fnp = 0, flp = -1;
        for (int w = 0; w < NW; w++) {
            fc += sh[0][w]; fb += sh[1][w]; fs += sh[2][w]; fn += sh[3][w];
            fnp += shi[0][w]; flp = max(flp, shi[1][w]);
        }
        double npos = (double)fnp;
        double nneg = (double)V - npos;
        out[0] = (float)(fc / (double)V);
        out[1] = (float)(fb / npos);
        out[2] = (float)(fs / npos);
        out[3] = (float)(fn / nneg);
        float sq = 0.0f;
        if (flp >= 0) {
            int a = vidx[flp];
            float4 p = bbox[a];
            float4 t = gt[a];
            float dx = p.x - t.x, dy = p.y - t.y, dz = p.z - t.z, dw = p.w - t.w;
            sq = 0.5f * (dx * dx + dy * dy + dz * dz + dw * dw);
        }
        out[4] = (float)((double)sq / npos);
    }
}

extern "C" void kernel_launch(void* const* d_in, const int* in_sizes, int n_in,
                              void* d_out, int out_size) {
    const float4* bbox   = (const float4*)d_in[0];  // [1,4M,4] f32
    const float2* logits = (const float2*)d_in[1];  // [1,4M,2] f32
    const float4* sigma  = (const float4*)d_in[2];  // [1,4M,4] f32
    const float4* gt     = (const float4*)d_in[3];  // [1,4M,4] f32
    const int*    label  = (const int*)d_in[4];     // [1,4M] i32
    const int*    vidx   = (const int*)d_in[5];     // [V] i32
    float* out = (float*)d_out;
    int V = in_sizes[5];

    int blocks = (V + TPB * VPT - 1) / (TPB * VPT);
    if (blocks > NBLK) blocks = NBLK;
    rpn_reduce_kernel<<<blocks, TPB>>>(bbox, logits, sigma, gt, label, vidx, V);
    rpn_finalize_kernel<<<1, TPB>>>(bbox, gt, vidx, out, V, blocks);
}

// round 4
// speedup vs baseline: 1.0046x; 1.0046x over previous
#include <cuda_runtime.h>

#define TPB 256
#define VPT 2

// Scalar accumulators (device globals — no allocation allowed).
// g_sums: [0]=class, [1]=bbox, [2]=sigma, [3]=neg, [4]=n_pos
__device__ double g_sums[5];
__device__ int    g_last_pos;

__global__ void rpn_zero_kernel() {
    int t = threadIdx.x;
    if (t < 5) g_sums[t] = 0.0;
    if (t == 5) g_last_pos = -1;
}

__inline__ __device__ double warp_sum_d(double v) {
    #pragma unroll
    for (int o = 16; o > 0; o >>= 1) v += __shfl_down_sync(0xffffffffu, v, o);
    return v;
}
__inline__ __device__ int warp_sum_i(int v) {
    #pragma unroll
    for (int o = 16; o > 0; o >>= 1) v += __shfl_down_sync(0xffffffffu, v, o);
    return v;
}
__inline__ __device__ int warp_max_i(int v) {
    #pragma unroll
    for (int o = 16; o > 0; o >>= 1) v = max(v, __shfl_down_sync(0xffffffffu, v, o));
    return v;
}

__global__ __launch_bounds__(TPB)
void rpn_reduce_kernel(const float4* __restrict__ bbox,   // [4M]
                       const float2* __restrict__ logits, // [4M]
                       const float4* __restrict__ sigma,  // [4M]
                       const float4* __restrict__ gt,     // [4M]
                       const int* __restrict__ label,     // [4M]
                       const int* __restrict__ vidx,      // [V]
                       int V) {
    const float EPS = 1e-10f;

    int i0 = (blockIdx.x * TPB + threadIdx.x) * VPT;

    // Gather phase: issue all loads for both elements before consuming.
    int   idx[VPT];
    int   lbl[VPT];
    float2 lg[VPT];
    float4 p[VPT], t[VPT], s[VPT];

    bool live0 = (i0 < V);
    bool live1 = (i0 + 1 < V);
    if (live1) {
        int2 a2 = *reinterpret_cast<const int2*>(vidx + i0);
        idx[0] = a2.x; idx[1] = a2.y;
    } else {
        idx[0] = live0 ? vidx[i0] : 0;
        idx[1] = idx[0];
    }

    #pragma unroll
    for (int j = 0; j < VPT; j++) {
        int a = idx[j];
        lbl[j] = label[a];
        lg[j]  = logits[a];
        p[j]   = bbox[a];
        t[j]   = gt[a];
        s[j]   = sigma[a];
    }

    double acc_c = 0.0, acc_b = 0.0, acc_s = 0.0, acc_n = 0.0;
    int npos = 0, lastp = -1;
    bool livej[VPT] = {live0, live1};

    #pragma unroll
    for (int j = 0; j < VPT; j++) {
        bool pos = (lbl[j] == 1);

        // -log_softmax at label (stable 2-class LSE), fast-math MUFU path
        float m   = fmaxf(lg[j].x, lg[j].y);
        float d   = -fabsf(lg[j].x - lg[j].y);
        float lse = m + __logf(1.0f + __expf(d));
        float sel = pos ? lg[j].y : lg[j].x;
        float cls = lse - sel;

        float dx = p[j].x - t[j].x, dy = p[j].y - t[j].y,
              dz = p[j].z - t[j].z, dw = p[j].w - t[j].w;
        float e0 = EPS + s[j].x, e1 = EPS + s[j].y,
              e2 = EPS + s[j].z, e3 = EPS + s[j].w;
        float r0 = __fdividef(1.0f, e0), r1 = __fdividef(1.0f, e1),
              r2 = __fdividef(1.0f, e2), r3 = __fdividef(1.0f, e3);

        float bsum = 0.5f * (dx * dx * r0 + dy * dy * r1 +
                             dz * dz * r2 + dw * dw * r3);
        float lsum = 0.5f * (__logf(e0 * e1) + __logf(e2 * e3));
        float nsum = r0 + r1 + r2 + r3;

        if (livej[j]) {
            acc_c += (double)cls;
            if (pos) {
                acc_b += (double)bsum;
                acc_s += (double)lsum;
                npos++;
                lastp = i0 + j;
            } else {
                acc_n += (double)nsum;
            }
        }
    }

    // Block reduction: warp shuffle -> shared -> warp 0 -> atomics
    __shared__ double sh[4][TPB / 32];
    __shared__ int    shi[2][TPB / 32];
    int lane = threadIdx.x & 31;
    int wid  = threadIdx.x >> 5;

    acc_c = warp_sum_d(acc_c);
    acc_b = warp_sum_d(acc_b);
    acc_s = warp_sum_d(acc_s);
    acc_n = warp_sum_d(acc_n);
    npos  = warp_sum_i(npos);
    lastp = warp_max_i(lastp);
    if (lane == 0) {
        sh[0][wid] = acc_c; sh[1][wid] = acc_b;
        sh[2][wid] = acc_s; sh[3][wid] = acc_n;
        shi[0][wid] = npos; shi[1][wid] = lastp;
    }
    __syncthreads();
    if (wid == 0) {
        const int NW = TPB / 32;
        double c  = (lane < NW) ? sh[0][lane] : 0.0;
        double b  = (lane < NW) ? sh[1][lane] : 0.0;
        double s2 = (lane < NW) ? sh[2][lane] : 0.0;
        double n2 = (lane < NW) ? sh[3][lane] : 0.0;
        int np = (lane < NW) ? shi[0][lane] : 0;
        int lp = (lane < NW) ? shi[1][lane] : -1;
        c = warp_sum_d(c); b = warp_sum_d(b);
        s2 = warp_sum_d(s2); n2 = warp_sum_d(n2);
        np = warp_sum_i(np); lp = warp_max_i(lp);
        if (lane == 0) {
            atomicAdd(&g_sums[0], c);
            atomicAdd(&g_sums[1], b);
            atomicAdd(&g_sums[2], s2);
            atomicAdd(&g_sums[3], n2);
            atomicAdd(&g_sums[4], (double)np);
            atomicMax(&g_last_pos, lp);
        }
    }
}

__global__ void rpn_finalize_kernel(const float4* __restrict__ bbox,
                                    const float4* __restrict__ gt,
                                    const int* __restrict__ vidx,
                                    float* __restrict__ out, int V) {
    if (threadIdx.x == 0) {
        double npos = g_sums[4];
        double nneg = (double)V - npos;
        out[0] = (float)(g_sums[0] / (double)V);
        out[1] = (float)(g_sums[1] / npos);
        out[2] = (float)(g_sums[2] / npos);
        out[3] = (float)(g_sums[3] / nneg);
        int lp = g_last_pos;
        float sq = 0.0f;
        if (lp >= 0) {
            int a = vidx[lp];
            float4 p = bbox[a];
            float4 t = gt[a];
            float dx = p.x - t.x, dy = p.y - t.y, dz = p.z - t.z, dw = p.w - t.w;
            sq = 0.5f * (dx * dx + dy * dy + dz * dz + dw * dw);
        }
        out[4] = (float)((double)sq / npos);
    }
}

extern "C" void kernel_launch(void* const* d_in, const int* in_sizes, int n_in,
                              void* d_out, int out_size) {
    const float4* bbox   = (const float4*)d_in[0];  // [1,4M,4] f32
    const float2* logits = (const float2*)d_in[1];  // [1,4M,2] f32
    const float4* sigma  = (const float4*)d_in[2];  // [1,4M,4] f32
    const float4* gt     = (const float4*)d_in[3];  // [1,4M,4] f32
    const int*    label  = (const int*)d_in[4];     // [1,4M] i32
    const int*    vidx   = (const int*)d_in[5];     // [V] i32
    float* out = (float*)d_out;
    int V = in_sizes[5];

    rpn_zero_kernel<<<1, 32>>>();
    int blocks = (V + TPB * VPT - 1) / (TPB * VPT);
    rpn_reduce_kernel<<<blocks, TPB>>>(bbox, logits, sigma, gt, label, vidx, V);
    rpn_finalize_kernel<<<1, 32>>>(bbox, gt, vidx, out, V);
}

// round 5
// speedup vs baseline: 1.8628x; 1.8544x over previous
#include <cuda_runtime.h>

#define TPB 256
#define NBLK 2048

// Scalar accumulators (device globals — zero-initialized at load; the
// finalize kernel resets them after each call, so every kernel_launch
// starts from zeros -> deterministic under graph replay).
// g_sums: [0]=class, [1]=bbox, [2]=sigma, [3]=neg, [4]=n_pos
__device__ double g_sums[5];
__device__ int    g_last_pos;  // reset to -1 by finalize; init below

// static initializer for the very first call
__device__ int g_last_init = 0;  // unused marker

__inline__ __device__ float warp_sum_f(float v) {
    #pragma unroll
    for (int o = 16; o > 0; o >>= 1) v += __shfl_down_sync(0xffffffffu, v, o);
    return v;
}
__inline__ __device__ int warp_sum_i(int v) {
    #pragma unroll
    for (int o = 16; o > 0; o >>= 1) v += __shfl_down_sync(0xffffffffu, v, o);
    return v;
}
__inline__ __device__ int warp_max_i(int v) {
    #pragma unroll
    for (int o = 16; o > 0; o >>= 1) v = max(v, __shfl_down_sync(0xffffffffu, v, o));
    return v;
}

__global__ void rpn_reduce_kernel(const float4* __restrict__ bbox,   // [4M]
                                  const float2* __restrict__ logits, // [4M]
                                  const float4* __restrict__ sigma,  // [4M]
                                  const float4* __restrict__ gt,     // [4M]
                                  const int* __restrict__ label,     // [4M]
                                  const int* __restrict__ vidx,      // [V]
                                  int V) {
    const float EPS = 1e-10f;
    float acc_c = 0.0f, acc_b = 0.0f, acc_s = 0.0f, acc_n = 0.0f;
    int npos = 0, lastp = -1;

    for (int i = blockIdx.x * blockDim.x + threadIdx.x; i < V;
         i += gridDim.x * blockDim.x) {
        int a = vidx[i];
        int lbl = label[a];
        float2 lg = logits[a];
        float4 p = bbox[a];
        float4 t = gt[a];
        float4 s = sigma[a];

        bool pos = (lbl == 1);

        // -log_softmax at label (stable 2-class LSE)
        float m   = fmaxf(lg.x, lg.y);
        float d   = -fabsf(lg.x - lg.y);
        float lse = m + __logf(1.0f + __expf(d));
        float sel = pos ? lg.y : lg.x;
        acc_c += (lse - sel);

        float dx = p.x - t.x, dy = p.y - t.y, dz = p.z - t.z, dw = p.w - t.w;
        float e0 = EPS + s.x, e1 = EPS + s.y, e2 = EPS + s.z, e3 = EPS + s.w;
        float r0 = __fdividef(1.0f, e0), r1 = __fdividef(1.0f, e1),
              r2 = __fdividef(1.0f, e2), r3 = __fdividef(1.0f, e3);

        if (pos) {
            acc_b += 0.5f * (dx * dx * r0 + dy * dy * r1 +
                             dz * dz * r2 + dw * dw * r3);
            acc_s += 0.5f * (__logf(e0 * e1) + __logf(e2 * e3));
            npos++;
            lastp = i;
        } else {
            acc_n += (r0 + r1 + r2 + r3);
        }
    }

    // Block reduction in fp32: warp shuffle -> shared -> warp 0 -> one
    // double atomic per block per quantity.
    __shared__ float sh[4][TPB / 32];
    __shared__ int   shi[2][TPB / 32];
    int lane = threadIdx.x & 31;
    int wid  = threadIdx.x >> 5;

    acc_c = warp_sum_f(acc_c);
    acc_b = warp_sum_f(acc_b);
    acc_s = warp_sum_f(acc_s);
    acc_n = warp_sum_f(acc_n);
    npos  = warp_sum_i(npos);
    lastp = warp_max_i(lastp);
    if (lane == 0) {
        sh[0][wid] = acc_c; sh[1][wid] = acc_b;
        sh[2][wid] = acc_s; sh[3][wid] = acc_n;
        shi[0][wid] = npos; shi[1][wid] = lastp;
    }
    __syncthreads();
    if (wid == 0) {
        const int NW = TPB / 32;
        float c  = (lane < NW) ? sh[0][lane] : 0.0f;
        float b  = (lane < NW) ? sh[1][lane] : 0.0f;
        float s2 = (lane < NW) ? sh[2][lane] : 0.0f;
        float n2 = (lane < NW) ? sh[3][lane] : 0.0f;
        int np = (lane < NW) ? shi[0][lane] : 0;
        int lp = (lane < NW) ? shi[1][lane] : -1;
        c = warp_sum_f(c); b = warp_sum_f(b);
        s2 = warp_sum_f(s2); n2 = warp_sum_f(n2);
        np = warp_sum_i(np); lp = warp_max_i(lp);
        if (lane == 0) {
            atomicAdd(&g_sums[0], (double)c);
            atomicAdd(&g_sums[1], (double)b);
            atomicAdd(&g_sums[2], (double)s2);
            atomicAdd(&g_sums[3], (double)n2);
            atomicAdd(&g_sums[4], (double)np);
            atomicMax(&g_last_pos, lp + 1);  // store lp+1 so initial 0 == "none"
        }
    }
}

__global__ void rpn_finalize_kernel(const float4* __restrict__ bbox,
                                    const float4* __restrict__ gt,
                                    const int* __restrict__ vidx,
                                    float* __restrict__ out, int V) {
    if (threadIdx.x == 0) {
        double npos = g_sums[4];
        double nneg = (double)V - npos;
        out[0] = (float)(g_sums[0] / (double)V);
        out[1] = (float)(g_sums[1] / npos);
        out[2] = (float)(g_sums[2] / npos);
        out[3] = (float)(g_sums[3] / nneg);
        int lp = g_last_pos - 1;  // undo +1 bias
        float sq = 0.0f;
        if (lp >= 0) {
            int a = vidx[lp];
            float4 p = bbox[a];
            float4 t = gt[a];
            float dx = p.x - t.x, dy = p.y - t.y, dz = p.z - t.z, dw = p.w - t.w;
            sq = 0.5f * (dx * dx + dy * dy + dz * dz + dw * dw);
        }
        out[4] = (float)((double)sq / npos);
        // Reset accumulators for the next (graph-replayed) call.
        g_sums[0] = 0.0; g_sums[1] = 0.0; g_sums[2] = 0.0;
        g_sums[3] = 0.0; g_sums[4] = 0.0;
        g_last_pos = 0;
    }
}

extern "C" void kernel_launch(void* const* d_in, const int* in_sizes, int n_in,
                              void* d_out, int out_size) {
    const float4* bbox   = (const float4*)d_in[0];  // [1,4M,4] f32
    const float2* logits = (const float2*)d_in[1];  // [1,4M,2] f32
    const float4* sigma  = (const float4*)d_in[2];  // [1,4M,4] f32
    const float4* gt     = (const float4*)d_in[3];  // [1,4M,4] f32
    const int*    label  = (const int*)d_in[4];     // [1,4M] i32
    const int*    vidx   = (const int*)d_in[5];     // [V] i32
    float* out = (float*)d_out;
    int V = in_sizes[5];

    int blocks = (V + TPB - 1) / TPB;
    if (blocks > NBLK) blocks = NBLK;
    rpn_reduce_kernel<<<blocks, TPB>>>(bbox, logits, sigma, gt, label, vidx, V);
    rpn_finalize_kernel<<<1, 32>>>(bbox, gt, vidx, out, V);
}

// round 6
// speedup vs baseline: 1.8750x; 1.0065x over previous
#include <cuda_runtime.h>

#define TPB 256
#define NBLK 2048

// Device globals (zero-initialized at load; the last block of each call
// resets them, so every kernel_launch starts from zeros -> deterministic
// under graph replay).
// g_sums: [0]=class, [1]=bbox, [2]=sigma, [3]=neg, [4]=n_pos
__device__ double g_sums[5];
__device__ int    g_last_pos;   // stores lastp+1 (0 == none)
__device__ unsigned int g_done; // completion ticket counter

__inline__ __device__ float warp_sum_f(float v) {
    #pragma unroll
    for (int o = 16; o > 0; o >>= 1) v += __shfl_down_sync(0xffffffffu, v, o);
    return v;
}
__inline__ __device__ int warp_sum_i(int v) {
    #pragma unroll
    for (int o = 16; o > 0; o >>= 1) v += __shfl_down_sync(0xffffffffu, v, o);
    return v;
}
__inline__ __device__ int warp_max_i(int v) {
    #pragma unroll
    for (int o = 16; o > 0; o >>= 1) v = max(v, __shfl_down_sync(0xffffffffu, v, o));
    return v;
}

__global__ void rpn_reduce_kernel(const float4* __restrict__ bbox,   // [4M]
                                  const float2* __restrict__ logits, // [4M]
                                  const float4* __restrict__ sigma,  // [4M]
                                  const float4* __restrict__ gt,     // [4M]
                                  const int* __restrict__ label,     // [4M]
                                  const int* __restrict__ vidx,      // [V]
                                  float* __restrict__ out,
                                  int V) {
    const float EPS = 1e-10f;
    float acc_c = 0.0f, acc_b = 0.0f, acc_s = 0.0f, acc_n = 0.0f;
    int npos = 0, lastp = -1;

    for (int i = blockIdx.x * blockDim.x + threadIdx.x; i < V;
         i += gridDim.x * blockDim.x) {
        int a = vidx[i];
        int lbl = label[a];
        float2 lg = logits[a];
        float4 p = bbox[a];
        float4 t = gt[a];
        float4 s = sigma[a];

        bool pos = (lbl == 1);

        // -log_softmax at label (stable 2-class LSE)
        float m   = fmaxf(lg.x, lg.y);
        float d   = -fabsf(lg.x - lg.y);
        float lse = m + __logf(1.0f + __expf(d));
        float sel = pos ? lg.y : lg.x;
        acc_c += (lse - sel);

        float dx = p.x - t.x, dy = p.y - t.y, dz = p.z - t.z, dw = p.w - t.w;
        float e0 = EPS + s.x, e1 = EPS + s.y, e2 = EPS + s.z, e3 = EPS + s.w;
        float r0 = __fdividef(1.0f, e0), r1 = __fdividef(1.0f, e1),
              r2 = __fdividef(1.0f, e2), r3 = __fdividef(1.0f, e3);

        if (pos) {
            acc_b += 0.5f * (dx * dx * r0 + dy * dy * r1 +
                             dz * dz * r2 + dw * dw * r3);
            acc_s += 0.5f * (__logf(e0 * e1) + __logf(e2 * e3));
            npos++;
            lastp = i;
        } else {
            acc_n += (r0 + r1 + r2 + r3);
        }
    }

    // Block reduction in fp32: warp shuffle -> shared -> warp 0 -> one
    // double atomic per block per quantity.
    __shared__ float sh[4][TPB / 32];
    __shared__ int   shi[2][TPB / 32];
    int lane = threadIdx.x & 31;
    int wid  = threadIdx.x >> 5;

    acc_c = warp_sum_f(acc_c);
    acc_b = warp_sum_f(acc_b);
    acc_s = warp_sum_f(acc_s);
    acc_n = warp_sum_f(acc_n);
    npos  = warp_sum_i(npos);
    lastp = warp_max_i(lastp);
    if (lane == 0) {
        sh[0][wid] = acc_c; sh[1][wid] = acc_b;
        sh[2][wid] = acc_s; sh[3][wid] = acc_n;
        shi[0][wid] = npos; shi[1][wid] = lastp;
    }
    __syncthreads();
    if (wid == 0) {
        const int NW = TPB / 32;
        float c  = (lane < NW) ? sh[0][lane] : 0.0f;
        float b  = (lane < NW) ? sh[1][lane] : 0.0f;
        float s2 = (lane < NW) ? sh[2][lane] : 0.0f;
        float n2 = (lane < NW) ? sh[3][lane] : 0.0f;
        int np = (lane < NW) ? shi[0][lane] : 0;
        int lp = (lane < NW) ? shi[1][lane] : -1;
        c = warp_sum_f(c); b = warp_sum_f(b);
        s2 = warp_sum_f(s2); n2 = warp_sum_f(n2);
        np = warp_sum_i(np); lp = warp_max_i(lp);
        if (lane == 0) {
            atomicAdd(&g_sums[0], (double)c);
            atomicAdd(&g_sums[1], (double)b);
            atomicAdd(&g_sums[2], (double)s2);
            atomicAdd(&g_sums[3], (double)n2);
            atomicAdd(&g_sums[4], (double)np);
            atomicMax(&g_last_pos, lp + 1);  // lp+1 so 0 == "none"

            // Completion ticket: the LAST block to finish does the finalize.
            __threadfence();
            unsigned int ticket = atomicAdd(&g_done, 1u);
            if (ticket == gridDim.x - 1) {
                // Re-read accumulators through the atomic path (L2-coherent;
                // plain loads could hit stale L1 lines).
                double fc = atomicAdd(&g_sums[0], 0.0);
                double fb = atomicAdd(&g_sums[1], 0.0);
                double fs = atomicAdd(&g_sums[2], 0.0);
                double fn = atomicAdd(&g_sums[3], 0.0);
                double npos_d = atomicAdd(&g_sums[4], 0.0);
                int lpf = atomicMax(&g_last_pos, 0) - 1;
                double nneg = (double)V - npos_d;

                out[0] = (float)(fc / (double)V);
                out[1] = (float)(fb / npos_d);
                out[2] = (float)(fs / npos_d);
                out[3] = (float)(fn / nneg);
                float sq = 0.0f;
                if (lpf >= 0) {
                    int a = vidx[lpf];
                    float4 pp = bbox[a];
                    float4 tt = gt[a];
                    float dx = pp.x - tt.x, dy = pp.y - tt.y,
                          dz = pp.z - tt.z, dw = pp.w - tt.w;
                    sq = 0.5f * (dx * dx + dy * dy + dz * dz + dw * dw);
                }
                out[4] = (float)((double)sq / npos_d);

                // Reset all globals for the next (graph-replayed) call.
                g_sums[0] = 0.0; g_sums[1] = 0.0; g_sums[2] = 0.0;
                g_sums[3] = 0.0; g_sums[4] = 0.0;
                g_last_pos = 0;
                __threadfence();
                g_done = 0u;
            }
        }
    }
}

extern "C" void kernel_launch(void* const* d_in, const int* in_sizes, int n_in,
                              void* d_out, int out_size) {
    const float4* bbox   = (const float4*)d_in[0];  // [1,4M,4] f32
    const float2* logits = (const float2*)d_in[1];  // [1,4M,2] f32
    const float4* sigma  = (const float4*)d_in[2];  // [1,4M,4] f32
    const float4* gt     = (const float4*)d_in[3];  // [1,4M,4] f32
    const int*    label  = (const int*)d_in[4];     // [1,4M] i32
    const int*    vidx   = (const int*)d_in[5];     // [V] i32
    float* out = (float*)d_out;
    int V = in_sizes[5];

    int blocks = (V + TPB - 1) / TPB;
    if (blocks > NBLK) blocks = NBLK;
    rpn_reduce_kernel<<<blocks, TPB>>>(bbox, logits, sigma, gt, label, vidx,
                                       out, V);
}

// round 7
// speedup vs baseline: 2.1066x; 1.1235x over previous
#include <cuda_runtime.h>

#define TPB 256
#define NBLK 2048
#define VPT 2

// Device globals (zero-initialized at load; the last block of each call
// resets them -> deterministic under graph replay).
// g_sums: [0]=class, [1]=bbox, [2]=sigma, [3]=neg, [4]=n_pos
__device__ double g_sums[5];
__device__ int    g_last_pos;   // stores lastp+1 (0 == none)
__device__ unsigned int g_done; // completion ticket counter

__inline__ __device__ float warp_sum_f(float v) {
    #pragma unroll
    for (int o = 16; o > 0; o >>= 1) v += __shfl_down_sync(0xffffffffu, v, o);
    return v;
}
__inline__ __device__ int warp_sum_i(int v) {
    #pragma unroll
    for (int o = 16; o > 0; o >>= 1) v += __shfl_down_sync(0xffffffffu, v, o);
    return v;
}
__inline__ __device__ int warp_max_i(int v) {
    #pragma unroll
    for (int o = 16; o > 0; o >>= 1) v = max(v, __shfl_down_sync(0xffffffffu, v, o));
    return v;
}

__global__ void rpn_reduce_kernel(const float4* __restrict__ bbox,   // [4M]
                                  const float2* __restrict__ logits, // [4M]
                                  const float4* __restrict__ sigma,  // [4M]
                                  const float4* __restrict__ gt,     // [4M]
                                  const int* __restrict__ label,     // [4M]
                                  const int* __restrict__ vidx,      // [V]
                                  float* __restrict__ out,
                                  int V) {
    const float EPS = 1e-10f;
    float acc_c = 0.0f, acc_b = 0.0f, acc_s = 0.0f, acc_n = 0.0f;
    int npos = 0, lastp = -1;

    const int stride = gridDim.x * TPB * VPT;
    int i0 = (blockIdx.x * TPB + threadIdx.x) * VPT;

    // Prime the index pipeline.
    int ia = 0, ib = 0;
    if (i0 + 1 < V) {
        int2 a2 = *reinterpret_cast<const int2*>(vidx + i0);
        ia = a2.x; ib = a2.y;
    } else if (i0 < V) {
        ia = vidx[i0]; ib = ia;
    }

    for (; i0 < V; i0 += stride) {
        bool live0 = true;               // i0 < V guaranteed by loop condition
        bool live1 = (i0 + 1 < V);
        int a0 = ia, a1 = ib;

        // Issue all 10 gathers for this pair.
        int    lbl0 = label[a0],  lbl1 = label[a1];
        float2 lg0  = logits[a0], lg1  = logits[a1];
        float4 p0   = bbox[a0],   p1   = bbox[a1];
        float4 t0   = gt[a0],     t1   = gt[a1];
        float4 s0   = sigma[a0],  s1   = sigma[a1];

        // Prefetch next iteration's indices (overlaps with the math below).
        int inext = i0 + stride;
        if (inext + 1 < V) {
            int2 a2 = *reinterpret_cast<const int2*>(vidx + inext);
            ia = a2.x; ib = a2.y;
        } else if (inext < V) {
            ia = vidx[inext]; ib = ia;
        }

        #pragma unroll
        for (int j = 0; j < VPT; j++) {
            bool  live = (j == 0) ? live0 : live1;
            int   lbl  = (j == 0) ? lbl0 : lbl1;
            float2 lg  = (j == 0) ? lg0  : lg1;
            float4 p   = (j == 0) ? p0   : p1;
            float4 t   = (j == 0) ? t0   : t1;
            float4 s   = (j == 0) ? s0   : s1;

            bool pos = (lbl == 1);

            // -log_softmax at label (stable 2-class LSE)
            float m   = fmaxf(lg.x, lg.y);
            float d   = -fabsf(lg.x - lg.y);
            float lse = m + __logf(1.0f + __expf(d));
            float sel = pos ? lg.y : lg.x;
            float cls = lse - sel;

            float dx = p.x - t.x, dy = p.y - t.y, dz = p.z - t.z, dw = p.w - t.w;
            float e0 = EPS + s.x, e1 = EPS + s.y, e2 = EPS + s.z, e3 = EPS + s.w;
            float r0 = __fdividef(1.0f, e0), r1 = __fdividef(1.0f, e1),
                  r2 = __fdividef(1.0f, e2), r3 = __fdividef(1.0f, e3);

            float bsum = 0.5f * (dx * dx * r0 + dy * dy * r1 +
                                 dz * dz * r2 + dw * dw * r3);
            float lsum = 0.5f * (__logf(e0 * e1) + __logf(e2 * e3));
            float nsum = r0 + r1 + r2 + r3;

            if (live) {
                acc_c += cls;
                if (pos) {
                    acc_b += bsum;
                    acc_s += lsum;
                    npos++;
                    lastp = i0 + j;
                } else {
                    acc_n += nsum;
                }
            }
        }
    }

    // Block reduction in fp32 -> one double atomic per block per quantity.
    __shared__ float sh[4][TPB / 32];
    __shared__ int   shi[2][TPB / 32];
    int lane = threadIdx.x & 31;
    int wid  = threadIdx.x >> 5;

    acc_c = warp_sum_f(acc_c);
    acc_b = warp_sum_f(acc_b);
    acc_s = warp_sum_f(acc_s);
    acc_n = warp_sum_f(acc_n);
    npos  = warp_sum_i(npos);
    lastp = warp_max_i(lastp);
    if (lane == 0) {
        sh[0][wid] = acc_c; sh[1][wid] = acc_b;
        sh[2][wid] = acc_s; sh[3][wid] = acc_n;
        shi[0][wid] = npos; shi[1][wid] = lastp;
    }
    __syncthreads();
    if (wid == 0) {
        const int NW = TPB / 32;
        float c  = (lane < NW) ? sh[0][lane] : 0.0f;
        float b  = (lane < NW) ? sh[1][lane] : 0.0f;
        float s2 = (lane < NW) ? sh[2][lane] : 0.0f;
        float n2 = (lane < NW) ? sh[3][lane] : 0.0f;
        int np = (lane < NW) ? shi[0][lane] : 0;
        int lp = (lane < NW) ? shi[1][lane] : -1;
        c = warp_sum_f(c); b = warp_sum_f(b);
        s2 = warp_sum_f(s2); n2 = warp_sum_f(n2);
        np = warp_sum_i(np); lp = warp_max_i(lp);
        if (lane == 0) {
            atomicAdd(&g_sums[0], (double)c);
            atomicAdd(&g_sums[1], (double)b);
            atomicAdd(&g_sums[2], (double)s2);
            atomicAdd(&g_sums[3], (double)n2);
            atomicAdd(&g_sums[4], (double)np);
            atomicMax(&g_last_pos, lp + 1);  // lp+1 so 0 == "none"

            // Completion ticket: the LAST block finalizes.
            __threadfence();
            unsigned int ticket = atomicAdd(&g_done, 1u);
            if (ticket == gridDim.x - 1) {
                double fc = atomicAdd(&g_sums[0], 0.0);
                double fb = atomicAdd(&g_sums[1], 0.0);
                double fs = atomicAdd(&g_sums[2], 0.0);
                double fn = atomicAdd(&g_sums[3], 0.0);
                double npos_d = atomicAdd(&g_sums[4], 0.0);
                int lpf = atomicMax(&g_last_pos, 0) - 1;
                double nneg = (double)V - npos_d;

                out[0] = (float)(fc / (double)V);
                out[1] = (float)(fb / npos_d);
                out[2] = (float)(fs / npos_d);
                out[3] = (float)(fn / nneg);
                float sq = 0.0f;
                if (lpf >= 0) {
                    int a = vidx[lpf];
                    float4 pp = bbox[a];
                    float4 tt = gt[a];
                    float dx = pp.x - tt.x, dy = pp.y - tt.y,
                          dz = pp.z - tt.z, dw = pp.w - tt.w;
                    sq = 0.5f * (dx * dx + dy * dy + dz * dz + dw * dw);
                }
                out[4] = (float)((double)sq / npos_d);

                // Reset globals for the next (graph-replayed) call.
                g_sums[0] = 0.0; g_sums[1] = 0.0; g_sums[2] = 0.0;
                g_sums[3] = 0.0; g_sums[4] = 0.0;
                g_last_pos = 0;
                __threadfence();
                g_done = 0u;
            }
        }
    }
}

extern "C" void kernel_launch(void* const* d_in, const int* in_sizes, int n_in,
                              void* d_out, int out_size) {
    const float4* bbox   = (const float4*)d_in[0];  // [1,4M,4] f32
    const float2* logits = (const float2*)d_in[1];  // [1,4M,2] f32
    const float4* sigma  = (const float4*)d_in[2];  // [1,4M,4] f32
    const float4* gt     = (const float4*)d_in[3];  // [1,4M,4] f32
    const int*    label  = (const int*)d_in[4];     // [1,4M] i32
    const int*    vidx   = (const int*)d_in[5];     // [V] i32
    float* out = (float*)d_out;
    int V = in_sizes[5];

    int blocks = (V + TPB * VPT - 1) / (TPB * VPT);
    if (blocks > NBLK) blocks = NBLK;
    rpn_reduce_kernel<<<blocks, TPB>>>(bbox, logits, sigma, gt, label, vidx,
                                       out, V);
}